// round 8
// baseline (speedup 1.0000x reference)
#include <cuda_runtime.h>

#define Sv    512
#define Iv    32
#define Hv    128
#define Gv    512      // 4*H
#define NB    4        // batches per CTA
#define NT    512      // threads per CTA (one gate per thread)
#define NCTA  128      // 128 * 4 = 512 batches
#define KS    48       // weight rows (k) in shared memory (0..47)
#define KR    80       // weight rows (k) in registers   (48..127)

typedef unsigned long long ull;

// ---- device scratch (static allocation is allowed; no cudaMalloc) ----
__device__ float4 g_xg[(size_t)Sv * NCTA * Gv];   // [t][cta][g] -> {b0,b1,b2,b3}
__device__ float  g_hall[(size_t)Sv * 512 * Hv];  // [t][b][u]  decoder hidden states

static __device__ __forceinline__ ull pack2(float a, float b){
    ull r; asm("mov.b64 %0, {%1,%2};" : "=l"(r) : "f"(a), "f"(b)); return r;
}
static __device__ __forceinline__ ull dup2(float a){
    ull r; asm("mov.b64 %0, {%1,%1};" : "=l"(r) : "f"(a)); return r;
}
static __device__ __forceinline__ void unpack2(ull v, float& a, float& b){
    asm("mov.b64 {%0,%1}, %2;" : "=f"(a), "=f"(b) : "l"(v));
}
// Blackwell packed fp32x2 FMA: d = a*b + d (two independent fp32 lanes)
static __device__ __forceinline__ void ffma2(ull& d, ull a, ull b){
    asm("fma.rn.f32x2 %0, %1, %2, %0;" : "+l"(d) : "l"(a), "l"(b));
}
static __device__ __forceinline__ float sig_(float x){
    return __fdividef(1.f, 1.f + __expf(-x));
}
static __device__ __forceinline__ float tanh_(float x){
    float ax = fabsf(x);
    float t  = __expf(-2.f * ax);
    float r  = __fdividef(1.f - t, 1.f + t);
    return copysignf(r, x);
}

// =====================================================================
// Kernel 1: encoder x-projection  g_xg[t][cta][g] = {x[b,t,:]@Wih^T + bias}
// grid = 1024 (128 ctas x 8 time-chunks), block = 256 (gate pairs)
// =====================================================================
__global__ void __launch_bounds__(256, 1) xproj_kernel(
    const float* __restrict__ x, const float* __restrict__ Wih,
    const float* __restrict__ bih, const float* __restrict__ bhh)
{
    __shared__ float xs[2][Iv * NB];
    const int tid = threadIdx.x;
    const int c   = blockIdx.x & (NCTA - 1);
    const int tq  = blockIdx.x >> 7;               // 0..7
    const int bbase = c * NB;
    const int TCH = Sv / 8;                        // 64 steps per block

    ull wd0[Iv], wd1[Iv];                          // pre-duplicated weights
    #pragma unroll
    for (int k = 0; k < Iv; k++){
        wd0[k] = dup2(Wih[(2*tid)     * Iv + k]);
        wd1[k] = dup2(Wih[(2*tid + 1) * Iv + k]);
    }
    const ull bd0 = dup2(bih[2*tid]     + bhh[2*tid]);
    const ull bd1 = dup2(bih[2*tid + 1] + bhh[2*tid + 1]);

    const int t0 = tq * TCH;
    // stage first step
    if (tid < Iv * NB){
        int i = tid & 31, bb = tid >> 5;
        xs[0][i * NB + bb] = x[((size_t)(bbase + bb) * Sv + t0) * Iv + i];
    }
    __syncthreads();

    int buf = 0;
    for (int tt = 0; tt < TCH; tt++){
        int t = t0 + tt;
        // stage next step into other buffer (no dependency on current reads)
        if (tt + 1 < TCH && tid < Iv * NB){
            int i = tid & 31, bb = tid >> 5;
            xs[buf ^ 1][i * NB + bb] =
                x[((size_t)(bbase + bb) * Sv + t + 1) * Iv + i];
        }
        ull a0 = bd0, a1 = bd0, a2 = bd1, a3 = bd1;
        #pragma unroll
        for (int k = 0; k < Iv; k++){
            ulonglong2 h = *(const ulonglong2*)(xs[buf] + k * NB);
            ffma2(a0, h.x, wd0[k]); ffma2(a1, h.y, wd0[k]);
            ffma2(a2, h.x, wd1[k]); ffma2(a3, h.y, wd1[k]);
        }
        float4 o0, o1;
        unpack2(a0, o0.x, o0.y); unpack2(a1, o0.z, o0.w);
        unpack2(a2, o1.x, o1.y); unpack2(a3, o1.z, o1.w);
        size_t base = ((size_t)t * NCTA + c) * Gv + 2*tid;
        g_xg[base]     = o0;
        g_xg[base + 1] = o1;
        __syncthreads();
        buf ^= 1;
    }
}

// =====================================================================
// Kernel 2: persistent recurrence (encoder + decoder), 128 CTAs x 512
// =====================================================================
#define OFF_WS    0                      // float Ws[KS][Gv]    98304 B
#define OFF_GACT  98304                  // float gact[NB][Gv]   8192 B
#define OFF_HS4   106496                 // float hs4[Hv][NB]    2048 B
#define SMEM_BYTES 108544

__global__ void __launch_bounds__(NT, 1) lstm_ae_kernel(
    const float* __restrict__ eWhh,
    const float* __restrict__ dWih, const float* __restrict__ dWhh,
    const float* __restrict__ dBih, const float* __restrict__ dBhh)
{
    extern __shared__ char smem[];
    float* Ws   = (float*)(smem + OFF_WS);
    float* gact = (float*)(smem + OFF_GACT);
    float* hs4  = (float*)(smem + OFF_HS4);

    const int tid   = threadIdx.x;           // gate index g
    const int gt    = tid >> 7;              // 0:i 1:f 2:g 3:o
    const int cta   = blockIdx.x;
    const int bbase = cta * NB;
    const int u     = tid & (Hv - 1);        // epilogue unit
    const int b     = tid >> 7;              // epilogue batch (1 item/thread)
    float wr[KR];                            // register weights rows 48..127
    float creg = 0.f;                        // cell state in register

    // ---------------- encoder setup ----------------
    for (int idx = tid; idx < Gv * KS; idx += NT){
        int r = idx >> 9, g = idx & (Gv - 1);
        Ws[idx] = eWhh[g * Hv + r];
    }
    #pragma unroll
    for (int kk = 0; kk < KR; kk++)
        wr[kk] = eWhh[tid * Hv + KS + kk];
    hs4[tid] = 0.f;                          // NT == Hv*NB
    // preload x-gates for t=0
    float4 xc;
    xc = g_xg[(size_t)cta * Gv + tid];
    __syncthreads();

    const float* wp = Ws + tid;
    const float* gA = gact + b * Gv;

    // ---------------- encoder loop ----------------
    for (int t = 0; t < Sv; t++){
        float4 xn = xc;
        if (t + 1 < Sv)
            xn = g_xg[((size_t)(t + 1) * NCTA + cta) * Gv + tid];

        ull a0 = pack2(xc.x, xc.y), a1 = pack2(xc.z, xc.w);

        #pragma unroll 12
        for (int k = 0; k < KS; k++){
            ulonglong2 h = *(const ulonglong2*)(hs4 + k * NB);
            ull wd = dup2(wp[k * Gv]);
            ffma2(a0, h.x, wd); ffma2(a1, h.y, wd);
        }
        #pragma unroll
        for (int kk = 0; kk < KR; kk++){
            ulonglong2 h = *(const ulonglong2*)(hs4 + (KS + kk) * NB);
            ull wd = dup2(wr[kk]);
            ffma2(a0, h.x, wd); ffma2(a1, h.y, wd);
        }
        {   // activations -> gact[b][g]
            float s0, s1, s2, s3;
            unpack2(a0, s0, s1); unpack2(a1, s2, s3);
            float v0, v1, v2, v3;
            if (gt == 2){ v0 = tanh_(s0); v1 = tanh_(s1); v2 = tanh_(s2); v3 = tanh_(s3); }
            else        { v0 = sig_(s0);  v1 = sig_(s1);  v2 = sig_(s2);  v3 = sig_(s3);  }
            gact[tid]          = v0;
            gact[Gv + tid]     = v1;
            gact[2*Gv + tid]   = v2;
            gact[3*Gv + tid]   = v3;
        }
        __syncthreads();                               // B1: gact ready
        {   // c,h update: c lives in register (1 item per thread)
            float iv = gA[u], fv = gA[Hv+u], gvv = gA[2*Hv+u], ov = gA[3*Hv+u];
            creg = fv * creg + iv * gvv;
            hs4[u * NB + b] = ov * tanh_(creg);
        }
        xc = xn;
        __syncthreads();                               // B2: h ready
    }
    // creg now holds enc_c (read-only in decoder); hs4 holds enc_h

    // ---------------- decoder setup ----------------
    for (int idx = tid; idx < Gv * KS; idx += NT){
        int r = idx >> 9, g = idx & (Gv - 1);
        Ws[idx] = dWhh[g * Hv + r];
    }
    #pragma unroll
    for (int kk = 0; kk < KR; kk++)
        wr[kk] = dWhh[tid * Hv + KS + kk];
    const ull bd = dup2(dBih[tid] + dBhh[tid]);
    float* hallp = g_hall + (size_t)(bbase + b) * Hv + u;   // + t*512*Hv
    __syncthreads();

    // ---------------- decoder loop ----------------
    for (int t = 0; t < Sv; t++){
        ull a0 = bd, a1 = bd;

        #pragma unroll 12
        for (int k = 0; k < KS; k++){
            ulonglong2 h = *(const ulonglong2*)(hs4 + k * NB);
            ull wd = dup2(wp[k * Gv]);
            ffma2(a0, h.x, wd); ffma2(a1, h.y, wd);
        }
        #pragma unroll
        for (int kk = 0; kk < KR; kk++){
            ulonglong2 h = *(const ulonglong2*)(hs4 + (KS + kk) * NB);
            ull wd = dup2(wr[kk]);
            ffma2(a0, h.x, wd); ffma2(a1, h.y, wd);
        }
        {
            float s0, s1, s2, s3;
            unpack2(a0, s0, s1); unpack2(a1, s2, s3);
            float v0, v1, v2, v3;
            if (gt == 2){ v0 = tanh_(s0); v1 = tanh_(s1); v2 = tanh_(s2); v3 = tanh_(s3); }
            else        { v0 = sig_(s0);  v1 = sig_(s1);  v2 = sig_(s2);  v3 = sig_(s3);  }
            gact[tid]          = v0;
            gact[Gv + tid]     = v1;
            gact[2*Gv + tid]   = v2;
            gact[3*Gv + tid]   = v3;
        }
        __syncthreads();                               // B1: gact ready
        {   // h update: cell input is ALWAYS enc_c (creg, read-only)
            float iv = gA[u], fv = gA[Hv+u], gvv = gA[2*Hv+u], ov = gA[3*Hv+u];
            float cn = fv * creg + iv * gvv;
            float hn = ov * tanh_(cn);
            hs4[u * NB + b] = hn;
            hallp[(size_t)t * 512 * Hv] = hn;          // fc deferred to kernel 3
        }
        if (t == 0){
            // in place: Whh -> Whh + Wih (steps >=1 have inp == h)
            for (int idx = tid; idx < Gv * KS; idx += NT){
                int r = idx >> 9, g = idx & (Gv - 1);
                Ws[idx] += dWih[g * Hv + r];
            }
            #pragma unroll
            for (int kk = 0; kk < KR; kk++)
                wr[kk] += dWih[tid * Hv + KS + kk];
        }
        __syncthreads();                               // B2: h/Ws ready
    }
}

// =====================================================================
// Kernel 3: deferred fc  out[b,t,:] = g_hall[t,b,:]@fcW^T + fcB
// grid = 4096 (64 rows each), block = 256
// =====================================================================
__global__ void __launch_bounds__(256, 1) fc_kernel(
    const float* __restrict__ fcW, const float* __restrict__ fcB,
    float* __restrict__ out)
{
    __shared__ ull   wsm[64 * 32];      // 16 KB packed fcW pairs
    __shared__ float hsm[64 * Hv];      // 32 KB staged h rows
    const int tid = threadIdx.x;

    for (int idx = tid; idx < 2048; idx += 256){
        int o = idx & 31, k2 = idx >> 5;
        wsm[idx] = pack2(fcW[o * Hv + 2*k2], fcW[o * Hv + 2*k2 + 1]);
    }
    const size_t rbase = (size_t)blockIdx.x * 64;      // row r = t*512 + b
    {   const float4* hg = (const float4*)(g_hall + rbase * Hv);
        float4* hd = (float4*)hsm;
        #pragma unroll
        for (int i = 0; i < 8; i++) hd[tid + i * 256] = hg[tid + i * 256];
    }
    __syncthreads();

    const int o = tid & 31, wq = tid >> 5;
    const float fb = fcB[o];
    #pragma unroll
    for (int i = 0; i < 8; i++){
        int rloc = wq * 8 + i;
        const float* hr = hsm + rloc * Hv;
        ull s = 0ull;
        #pragma unroll 16
        for (int k2 = 0; k2 < Hv/2; k2++){
            ull h2 = *(const ull*)(hr + 2*k2);
            ffma2(s, h2, wsm[k2 * 32 + o]);
        }
        float sa, sb; unpack2(s, sa, sb);
        size_t r = rbase + rloc;
        size_t bb = r & 511, t = r >> 9;
        out[(bb * Sv + t) * Iv + o] = sa + sb + fb;
    }
}

extern "C" void kernel_launch(void* const* d_in, const int* in_sizes, int n_in,
                              void* d_out, int out_size)
{
    const float* x    = (const float*)d_in[0];
    const float* eWih = (const float*)d_in[1];
    const float* eWhh = (const float*)d_in[2];
    const float* eBih = (const float*)d_in[3];
    const float* eBhh = (const float*)d_in[4];
    const float* dWih = (const float*)d_in[5];
    const float* dWhh = (const float*)d_in[6];
    const float* dBih = (const float*)d_in[7];
    const float* dBhh = (const float*)d_in[8];
    const float* fcW  = (const float*)d_in[9];
    const float* fcB  = (const float*)d_in[10];
    float* out = (float*)d_out;

    cudaFuncSetAttribute(lstm_ae_kernel,
                         cudaFuncAttributeMaxDynamicSharedMemorySize, SMEM_BYTES);
    xproj_kernel<<<1024, 256>>>(x, eWih, eBih, eBhh);
    lstm_ae_kernel<<<NCTA, NT, SMEM_BYTES>>>(eWhh, dWih, dWhh, dBih, dBhh);
    fc_kernel<<<4096, 256>>>(fcW, fcB, out);
}

// round 9
// speedup vs baseline: 1.2446x; 1.2446x over previous
#include <cuda_runtime.h>

#define Sv    512
#define Iv    32
#define Hv    128
#define Gv    512      // 4*H
#define NB    4        // batches per CTA
#define NT    512      // threads per CTA
#define NCTA  128      // 128 * 4 = 512 batches

typedef unsigned long long ull;

// ---- device scratch (static allocation is allowed; no cudaMalloc) ----
__device__ float4 g_xg[(size_t)Sv * NCTA * Gv];   // [t][cta][g] -> {b0,b1,b2,b3}
__device__ float  g_hall[(size_t)Sv * 512 * Hv];  // [t][b][u]  decoder hidden states

static __device__ __forceinline__ ull pack2(float a, float b){
    ull r; asm("mov.b64 %0, {%1,%2};" : "=l"(r) : "f"(a), "f"(b)); return r;
}
static __device__ __forceinline__ ull dup2(float a){
    ull r; asm("mov.b64 %0, {%1,%1};" : "=l"(r) : "f"(a)); return r;
}
static __device__ __forceinline__ void unpack2(ull v, float& a, float& b){
    asm("mov.b64 {%0,%1}, %2;" : "=f"(a), "=f"(b) : "l"(v));
}
static __device__ __forceinline__ void ffma2(ull& d, ull a, ull b){
    asm("fma.rn.f32x2 %0, %1, %2, %0;" : "+l"(d) : "l"(a), "l"(b));
}
static __device__ __forceinline__ ull f2add(ull a, ull b){
    ull r; asm("add.rn.f32x2 %0, %1, %2;" : "=l"(r) : "l"(a), "l"(b)); return r;
}
static __device__ __forceinline__ float sig_(float x){
    return __fdividef(1.f, 1.f + __expf(-x));
}
static __device__ __forceinline__ float tanh_(float x){
    float ax = fabsf(x);
    float t  = __expf(-2.f * ax);
    float r  = __fdividef(1.f - t, 1.f + t);
    return copysignf(r, x);
}

// =====================================================================
// Kernel 1: streaming x-projection GEMM
//   g_xg[t][cta][g] = {x[b,t,:]@Wih^T + bias} for the cta's 4 batches
// grid = 2048 (128 ctas x 16 time-chunks of 32), block = 512 (1 gate each)
// =====================================================================
#define XP_SMEM (64*1024 + 16*1024)
__global__ void __launch_bounds__(512, 1) xproj_kernel(
    const float* __restrict__ x, const float* __restrict__ Wih,
    const float* __restrict__ bih, const float* __restrict__ bhh)
{
    extern __shared__ float xsm[];
    float* Wsm = xsm;                  // [32][512]  64 KB
    float* xs  = xsm + 32*512;         // [32][32][4] 16 KB
    const int tid = threadIdx.x;
    const int c   = blockIdx.x & (NCTA - 1);
    const int tq  = blockIdx.x >> 7;               // 0..15
    const int t0  = tq * 32;
    const int bbase = c * NB;

    for (int idx = tid; idx < 32*512; idx += 512){
        int k = idx & 31, g = idx >> 5;
        Wsm[k * 512 + g] = Wih[g * Iv + k];
    }
    for (int idx = tid; idx < 32*32*4; idx += 512){
        int i = idx & 31, tt = (idx >> 5) & 31, b = idx >> 10;
        xs[(tt * 32 + i) * 4 + b] =
            x[((size_t)(bbase + b) * Sv + t0 + tt) * Iv + i];
    }
    const ull bd = dup2(bih[tid] + bhh[tid]);
    __syncthreads();

    float4* xg4 = g_xg;
    #pragma unroll 2
    for (int tt = 0; tt < 32; tt++){
        ull a0 = bd, a1 = bd;
        #pragma unroll
        for (int k = 0; k < 32; k++){
            ulonglong2 h = *(const ulonglong2*)(xs + (tt * 32 + k) * 4);
            ull wd = dup2(Wsm[k * 512 + tid]);
            ffma2(a0, h.x, wd); ffma2(a1, h.y, wd);
        }
        float4 o;
        unpack2(a0, o.x, o.y); unpack2(a1, o.z, o.w);
        xg4[((size_t)(t0 + tt) * NCTA + c) * Gv + tid] = o;
    }
}

// =====================================================================
// Kernel 2: persistent recurrence, 128 CTAs x 512 threads
//   Thread owns gate-pair gp = w*16 + (l&15); half = l>>4 owns k-range
//   half*64..half*64+63. Partials merged via shfl.bfly(16).
// =====================================================================
#define KSM   32                       // smem weight rows per half
#define KRG   32                       // register weight rows per half
#define OFF_WS    0                    // float Ws[64][Gv]   131072 B
#define OFF_GACT  131072               // float gact[NB][Gv]   8192 B
#define OFF_HS    139264               // float hs[516+pad]    2176 B
#define SMEM_BYTES 141440

__global__ void __launch_bounds__(NT, 1) lstm_ae_kernel(
    const float* __restrict__ eWhh,
    const float* __restrict__ dWih, const float* __restrict__ dWhh,
    const float* __restrict__ dBih, const float* __restrict__ dBhh)
{
    extern __shared__ char smem[];
    float* Ws   = (float*)(smem + OFF_WS);
    float* gact = (float*)(smem + OFF_GACT);
    float* hsf  = (float*)(smem + OFF_HS);   // h[k][b], rows k>=64 skewed +4 floats

    const int tid  = threadIdx.x;
    const int w    = tid >> 5;
    const int l    = tid & 31;
    const int half = l >> 4;                 // 0: k in [0,64), 1: k in [64,128)
    const int gp   = w * 16 + (l & 15);      // gate pair
    const int g0   = 2 * gp;
    const int gown = g0 + half;              // gate this thread activates
    const int gt   = w >> 2;                 // 0:i 1:f 2:g 3:o (warp-uniform)
    const int kbase = half * 64;
    const int cta  = blockIdx.x;
    const int ub   = tid & (Hv - 1);         // epilogue unit
    const int bb   = tid >> 7;               // epilogue batch
    float wra[KRG], wrb[KRG];                // reg weights rows kbase+32..kbase+63
    float creg = 0.f;

    // h row address helper: rows >=64 skewed by 4 floats (bank decorrelation)
    float* hbase = hsf + (half ? 260 : 0);   // MAC base: rows kbase.. -> hbase + 4*j

    // ---------------- encoder setup ----------------
    for (int idx = tid; idx < Gv * 64; idx += NT){
        int r = idx >> 9, g = idx & (Gv - 1);
        int k = (r < 32) ? r : (r + 32);
        Ws[idx] = eWhh[g * Hv + k];
    }
    #pragma unroll
    for (int j = 0; j < KRG; j++){
        wra[j] = eWhh[g0 * Hv + kbase + 32 + j];
        wrb[j] = eWhh[(g0 + 1) * Hv + kbase + 32 + j];
    }
    if (tid < 516) hsf[tid] = 0.f;
    if (tid < 4)   hsf[512 + tid] = 0.f;
    float4 xc = g_xg[(size_t)cta * Gv + gown];
    __syncthreads();

    const float* wp0 = Ws + (half * 32) * Gv + g0;   // smem weight base
    const float* gA  = gact + bb * Gv;

    // ---------------- encoder loop ----------------
    for (int t = 0; t < Sv; t++){
        float4 xn = xc;
        if (t + 1 < Sv)
            xn = g_xg[((size_t)(t + 1) * NCTA + cta) * Gv + gown];

        ull xa0 = pack2(xc.x, xc.y), xa1 = pack2(xc.z, xc.w);
        ull a0 = half ? 0ull : xa0, a1 = half ? 0ull : xa1;
        ull a2 = half ? xa0 : 0ull, a3 = half ? xa1 : 0ull;

        #pragma unroll
        for (int j = 0; j < KSM; j++){
            ulonglong2 h = *(const ulonglong2*)(hbase + 4 * j);
            float2 wv = *(const float2*)(wp0 + j * Gv);
            ull wd0 = dup2(wv.x), wd1 = dup2(wv.y);
            ffma2(a0, h.x, wd0); ffma2(a1, h.y, wd0);
            ffma2(a2, h.x, wd1); ffma2(a3, h.y, wd1);
        }
        #pragma unroll
        for (int j = 0; j < KRG; j++){
            ulonglong2 h = *(const ulonglong2*)(hbase + 128 + 4 * j);
            ull wd0 = dup2(wra[j]), wd1 = dup2(wrb[j]);
            ffma2(a0, h.x, wd0); ffma2(a1, h.y, wd0);
            ffma2(a2, h.x, wd1); ffma2(a3, h.y, wd1);
        }
        // merge k-halves (each lane ends with full sums for both gates)
        a0 = f2add(a0, __shfl_xor_sync(0xffffffffu, a0, 16));
        a1 = f2add(a1, __shfl_xor_sync(0xffffffffu, a1, 16));
        a2 = f2add(a2, __shfl_xor_sync(0xffffffffu, a2, 16));
        a3 = f2add(a3, __shfl_xor_sync(0xffffffffu, a3, 16));
        {   // activate own gate only
            ull m0 = half ? a2 : a0, m1 = half ? a3 : a1;
            float s0, s1, s2, s3;
            unpack2(m0, s0, s1); unpack2(m1, s2, s3);
            float v0, v1, v2, v3;
            if (gt == 2){ v0 = tanh_(s0); v1 = tanh_(s1); v2 = tanh_(s2); v3 = tanh_(s3); }
            else        { v0 = sig_(s0);  v1 = sig_(s1);  v2 = sig_(s2);  v3 = sig_(s3);  }
            gact[gown]          = v0;
            gact[Gv + gown]     = v1;
            gact[2*Gv + gown]   = v2;
            gact[3*Gv + gown]   = v3;
        }
        __syncthreads();                               // B1: gact ready
        {   // c,h update (1 item per thread), c in register
            float iv = gA[ub], fv = gA[Hv+ub], gvv = gA[2*Hv+ub], ov = gA[3*Hv+ub];
            creg = fv * creg + iv * gvv;
            hsf[ub * 4 + ((ub >= 64) ? 4 : 0) + bb] = ov * tanh_(creg);
        }
        xc = xn;
        __syncthreads();                               // B2: h ready
    }
    // creg holds enc_c (read-only below); hsf holds enc_h

    // ---------------- decoder setup ----------------
    for (int idx = tid; idx < Gv * 64; idx += NT){
        int r = idx >> 9, g = idx & (Gv - 1);
        int k = (r < 32) ? r : (r + 32);
        Ws[idx] = dWhh[g * Hv + k];
    }
    #pragma unroll
    for (int j = 0; j < KRG; j++){
        wra[j] = dWhh[g0 * Hv + kbase + 32 + j];
        wrb[j] = dWhh[(g0 + 1) * Hv + kbase + 32 + j];
    }
    const ull bdv = dup2(dBih[gown] + dBhh[gown]);
    float* hallp = g_hall + (size_t)(cta * NB + bb) * Hv + ub;   // + t*65536
    __syncthreads();

    // ---------------- decoder loop ----------------
    for (int t = 0; t < Sv; t++){
        ull a0 = half ? 0ull : bdv, a1 = half ? 0ull : bdv;
        ull a2 = half ? bdv : 0ull, a3 = half ? bdv : 0ull;

        #pragma unroll
        for (int j = 0; j < KSM; j++){
            ulonglong2 h = *(const ulonglong2*)(hbase + 4 * j);
            float2 wv = *(const float2*)(wp0 + j * Gv);
            ull wd0 = dup2(wv.x), wd1 = dup2(wv.y);
            ffma2(a0, h.x, wd0); ffma2(a1, h.y, wd0);
            ffma2(a2, h.x, wd1); ffma2(a3, h.y, wd1);
        }
        #pragma unroll
        for (int j = 0; j < KRG; j++){
            ulonglong2 h = *(const ulonglong2*)(hbase + 128 + 4 * j);
            ull wd0 = dup2(wra[j]), wd1 = dup2(wrb[j]);
            ffma2(a0, h.x, wd0); ffma2(a1, h.y, wd0);
            ffma2(a2, h.x, wd1); ffma2(a3, h.y, wd1);
        }
        a0 = f2add(a0, __shfl_xor_sync(0xffffffffu, a0, 16));
        a1 = f2add(a1, __shfl_xor_sync(0xffffffffu, a1, 16));
        a2 = f2add(a2, __shfl_xor_sync(0xffffffffu, a2, 16));
        a3 = f2add(a3, __shfl_xor_sync(0xffffffffu, a3, 16));
        {
            ull m0 = half ? a2 : a0, m1 = half ? a3 : a1;
            float s0, s1, s2, s3;
            unpack2(m0, s0, s1); unpack2(m1, s2, s3);
            float v0, v1, v2, v3;
            if (gt == 2){ v0 = tanh_(s0); v1 = tanh_(s1); v2 = tanh_(s2); v3 = tanh_(s3); }
            else        { v0 = sig_(s0);  v1 = sig_(s1);  v2 = sig_(s2);  v3 = sig_(s3);  }
            gact[gown]          = v0;
            gact[Gv + gown]     = v1;
            gact[2*Gv + gown]   = v2;
            gact[3*Gv + gown]   = v3;
        }
        __syncthreads();                               // B1: gact ready
        {   // h update: cell input is ALWAYS enc_c (creg, read-only)
            float iv = gA[ub], fv = gA[Hv+ub], gvv = gA[2*Hv+ub], ov = gA[3*Hv+ub];
            float cn = fv * creg + iv * gvv;
            float hn = ov * tanh_(cn);
            hsf[ub * 4 + ((ub >= 64) ? 4 : 0) + bb] = hn;
            hallp[(size_t)t * 512 * Hv] = hn;          // fc deferred to kernel 3
        }
        if (t == 0){
            // in place: Whh -> Whh + Wih (steps >=1 have inp == h)
            for (int idx = tid; idx < Gv * 64; idx += NT){
                int r = idx >> 9, g = idx & (Gv - 1);
                int k = (r < 32) ? r : (r + 32);
                Ws[idx] += dWih[g * Hv + k];
            }
            #pragma unroll
            for (int j = 0; j < KRG; j++){
                wra[j] += dWih[g0 * Hv + kbase + 32 + j];
                wrb[j] += dWih[(g0 + 1) * Hv + kbase + 32 + j];
            }
        }
        __syncthreads();                               // B2: h/Ws ready
    }
}

// =====================================================================
// Kernel 3: deferred fc  out[b,t,:] = g_hall[t,b,:]@fcW^T + fcB
// grid = 4096 (64 rows each), block = 256
// =====================================================================
__global__ void __launch_bounds__(256, 1) fc_kernel(
    const float* __restrict__ fcW, const float* __restrict__ fcB,
    float* __restrict__ out)
{
    __shared__ ull   wsm[64 * 32];      // 16 KB packed fcW pairs
    __shared__ float hsm[64 * Hv];      // 32 KB staged h rows
    const int tid = threadIdx.x;

    for (int idx = tid; idx < 2048; idx += 256){
        int o = idx & 31, k2 = idx >> 5;
        wsm[idx] = pack2(fcW[o * Hv + 2*k2], fcW[o * Hv + 2*k2 + 1]);
    }
    const size_t rbase = (size_t)blockIdx.x * 64;      // row r = t*512 + b
    {   const float4* hg = (const float4*)(g_hall + rbase * Hv);
        float4* hd = (float4*)hsm;
        #pragma unroll
        for (int i = 0; i < 8; i++) hd[tid + i * 256] = hg[tid + i * 256];
    }
    __syncthreads();

    const int o = tid & 31, wq = tid >> 5;
    const float fb = fcB[o];
    #pragma unroll
    for (int i = 0; i < 8; i++){
        int rloc = wq * 8 + i;
        const float* hr = hsm + rloc * Hv;
        ull s = 0ull;
        #pragma unroll 16
        for (int k2 = 0; k2 < Hv/2; k2++){
            ull h2 = *(const ull*)(hr + 2*k2);
            ffma2(s, h2, wsm[k2 * 32 + o]);
        }
        float sa, sb; unpack2(s, sa, sb);
        size_t r = rbase + rloc;
        size_t b2 = r & 511, t = r >> 9;
        out[(b2 * Sv + t) * Iv + o] = sa + sb + fb;
    }
}

extern "C" void kernel_launch(void* const* d_in, const int* in_sizes, int n_in,
                              void* d_out, int out_size)
{
    const float* x    = (const float*)d_in[0];
    const float* eWih = (const float*)d_in[1];
    const float* eWhh = (const float*)d_in[2];
    const float* eBih = (const float*)d_in[3];
    const float* eBhh = (const float*)d_in[4];
    const float* dWih = (const float*)d_in[5];
    const float* dWhh = (const float*)d_in[6];
    const float* dBih = (const float*)d_in[7];
    const float* dBhh = (const float*)d_in[8];
    const float* fcW  = (const float*)d_in[9];
    const float* fcB  = (const float*)d_in[10];
    float* out = (float*)d_out;

    cudaFuncSetAttribute(xproj_kernel,
                         cudaFuncAttributeMaxDynamicSharedMemorySize, XP_SMEM);
    cudaFuncSetAttribute(lstm_ae_kernel,
                         cudaFuncAttributeMaxDynamicSharedMemorySize, SMEM_BYTES);
    xproj_kernel<<<2048, 512, XP_SMEM>>>(x, eWih, eBih, eBhh);
    lstm_ae_kernel<<<NCTA, NT, SMEM_BYTES>>>(eWhh, dWih, dWhh, dBih, dBhh);
    fc_kernel<<<4096, 256>>>(fcW, fcB, out);
}